// round 2
// baseline (speedup 1.0000x reference)
#include <cuda_runtime.h>
#include <cuda_bf16.h>
#include <cstddef>

// Problem constants
#define BB   64
#define NN   4096
#define CC   64
#define OUT  64
#define K2   4
#define KDIM (K2 * CC)        // 256  GEMM K dimension (k,c flattened)
#define SITES 64              // sites per tile
#define XSTR 68               // padded row stride for Xs (16B aligned, de-conflicted)
#define NTILES (BB * (NN / SITES))   // 4096 tiles

#define SMEM_W_FLOATS  (KDIM * OUT)     // 16384 floats = 64 KB
#define SMEM_X_FLOATS  (KDIM * XSTR)    // 17408 floats = 68 KB
#define SMEM_BYTES     ((SMEM_W_FLOATS + SMEM_X_FLOATS) * 4)

__global__ __launch_bounds__(256, 1)
void conv_gather_gemm_kernel(const float* __restrict__ x,
                             const float* __restrict__ W,
                             const float* __restrict__ bias,
                             const int*   __restrict__ kernel2,
                             float*       __restrict__ out)
{
    extern __shared__ float sm[];
    float* Ws = sm;                       // [KDIM][OUT]   kc-major, matches W layout
    float* Xs = sm + SMEM_W_FLOATS;       // [KDIM][XSTR]  kc-major, site minor
    __shared__ int sidx[SITES * K2];      // gathered indices for this tile

    const int tid  = threadIdx.x;
    const int warp = tid >> 5;
    const int lane = tid & 31;
    const int tx   = tid & 15;            // output-column group (4 outs)
    const int ty   = tid >> 4;            // site group (4 sites)
    const int tx4  = tx << 2;
    const int ty4  = ty << 2;

    // ---- Load W once per block: 16384 floats as float4, fully coalesced ----
    {
        const float4* Wg = reinterpret_cast<const float4*>(W);
        float4*       Wd = reinterpret_cast<float4*>(Ws);
        #pragma unroll
        for (int i = 0; i < SMEM_W_FLOATS / 4 / 256; ++i)
            Wd[tid + i * 256] = Wg[tid + i * 256];
    }

    // Bias for this thread's 4 output columns (tile-invariant)
    const float4 bv = *reinterpret_cast<const float4*>(bias + tx4);

    __syncthreads();

    // ---- Grid-stride over 4096 tiles (batch-major for L2 locality on x) ----
    for (int tile = blockIdx.x; tile < NTILES; tile += gridDim.x) {
        const int b  = tile >> 6;              // 64 tiles per batch
        const int n0 = (tile & 63) * SITES;    // first site of tile

        // Load the 256 gather indices: sidx[s*4+k] = kernel2[(n0+s)*4 + k]
        sidx[tid] = kernel2[n0 * K2 + tid];
        __syncthreads();

        // ---- Gather x rows into Xs (transposed: Xs[k*64+c][site]) ----
        // One warp per (site,k) row; 2x 128B coalesced global loads per row.
        {
            const float* xb = x + (size_t)b * NN * CC;
            #pragma unroll
            for (int r = warp; r < SITES * K2; r += 8) {
                const int s  = r >> 2;
                const int k  = r & 3;
                const int gi = sidx[r];
                const float* src = xb + (size_t)gi * CC;
                const float v0 = src[lane];
                const float v1 = src[lane + 32];
                const int kc = k << 6;
                Xs[(kc + lane)      * XSTR + s] = v0;
                Xs[(kc + lane + 32) * XSTR + s] = v1;
            }
        }
        __syncthreads();

        // ---- 64x64 GEMM with K=256: 4x4 register microtile per thread ----
        float acc[4][4];
        #pragma unroll
        for (int i = 0; i < 4; ++i)
            #pragma unroll
            for (int j = 0; j < 4; ++j)
                acc[i][j] = 0.0f;

        #pragma unroll 4
        for (int kc = 0; kc < KDIM; ++kc) {
            const float4 a = *reinterpret_cast<const float4*>(Xs + kc * XSTR + ty4);
            const float4 w = *reinterpret_cast<const float4*>(Ws + (kc << 6) + tx4);
            acc[0][0] += a.x * w.x; acc[0][1] += a.x * w.y;
            acc[0][2] += a.x * w.z; acc[0][3] += a.x * w.w;
            acc[1][0] += a.y * w.x; acc[1][1] += a.y * w.y;
            acc[1][2] += a.y * w.z; acc[1][3] += a.y * w.w;
            acc[2][0] += a.z * w.x; acc[2][1] += a.z * w.y;
            acc[2][2] += a.z * w.z; acc[2][3] += a.z * w.w;
            acc[3][0] += a.w * w.x; acc[3][1] += a.w * w.y;
            acc[3][2] += a.w * w.z; acc[3][3] += a.w * w.w;
        }

        // ---- Bias + store (float4, coalesced across tx) ----
        {
            float* op = out + ((size_t)b * NN + n0 + ty4) * OUT + tx4;
            #pragma unroll
            for (int i = 0; i < 4; ++i) {
                float4 r;
                r.x = acc[i][0] + bv.x;
                r.y = acc[i][1] + bv.y;
                r.z = acc[i][2] + bv.z;
                r.w = acc[i][3] + bv.w;
                *reinterpret_cast<float4*>(op + (size_t)i * OUT) = r;
            }
        }
        __syncthreads();   // protect Xs/sidx before next tile's gather
    }
}

extern "C" void kernel_launch(void* const* d_in, const int* in_sizes, int n_in,
                              void* d_out, int out_size)
{
    const float* x    = (const float*)d_in[0];   // [B, N, C]
    const float* W    = (const float*)d_in[1];   // [K2, C, OUT]
    const float* bias = (const float*)d_in[2];   // [OUT]
    const int*   k2   = (const int*)d_in[3];     // [N, K2]
    float*       out  = (float*)d_out;           // [B, N, OUT]

    cudaFuncSetAttribute(conv_gather_gemm_kernel,
                         cudaFuncAttributeMaxDynamicSharedMemorySize, SMEM_BYTES);

    conv_gather_gemm_kernel<<<296, 256, SMEM_BYTES>>>(x, W, bias, k2, out);
}

// round 5
// speedup vs baseline: 2.1450x; 2.1450x over previous
#include <cuda_runtime.h>
#include <cuda_bf16.h>
#include <cstdint>
#include <cstddef>

// Problem constants
#define BB   64
#define NN   4096
#define CC   64
#define OUTF 64
#define K2   4
#define TM   128                       // sites per tile (GEMM M)
#define KDIM 256                       // GEMM K = K2*CC
#define NTILES 2048                    // BB * NN / TM
#define GRID 148
#define NTHREADS 256

#define ASTRB 528                      // row stride in bytes (264 bf16; odd 16B phase -> ldmatrix conflict-free)

// smem layout (bytes)
#define SM_BIAS 0                      // 64 floats
#define SM_SIDX 256                    // 512 ints
#define SM_AHI  2560                   // 128 rows * 528B = 67584
#define SM_ALO  (SM_AHI + TM * ASTRB)
#define SM_BHI  (SM_ALO + TM * ASTRB)  // 64 rows * 528B = 33792
#define SM_BLO  (SM_BHI + OUTF * ASTRB)
#define SM_TOTAL (SM_BLO + OUTF * ASTRB)   // 205312 bytes

__device__ __forceinline__ uint32_t smem_u32(const void* p) {
    uint32_t a;
    asm("{ .reg .u64 t; cvta.to.shared.u64 t, %1; cvt.u32.u64 %0, t; }" : "=r"(a) : "l"(p));
    return a;
}
__device__ __forceinline__ void ldsm_x4(uint32_t& r0, uint32_t& r1, uint32_t& r2, uint32_t& r3,
                                        uint32_t addr) {
    asm volatile("ldmatrix.sync.aligned.m8n8.x4.shared.b16 {%0,%1,%2,%3}, [%4];"
                 : "=r"(r0), "=r"(r1), "=r"(r2), "=r"(r3) : "r"(addr));
}
__device__ __forceinline__ void mma_bf16(float* acc, const uint32_t* a, const uint32_t* b) {
    asm volatile(
        "mma.sync.aligned.m16n8k16.row.col.f32.bf16.bf16.f32 "
        "{%0,%1,%2,%3}, {%4,%5,%6,%7}, {%8,%9}, {%0,%1,%2,%3};"
        : "+f"(acc[0]), "+f"(acc[1]), "+f"(acc[2]), "+f"(acc[3])
        : "r"(a[0]), "r"(a[1]), "r"(a[2]), "r"(a[3]), "r"(b[0]), "r"(b[1]));
}
__device__ __forceinline__ uint32_t pack_bf2(__nv_bfloat16 a, __nv_bfloat16 b) {
    __nv_bfloat162 t = __halves2bfloat162(a, b);
    uint32_t u;
    memcpy(&u, &t, 4);
    return u;
}

__global__ __launch_bounds__(NTHREADS, 1)
void conv_mma_kernel(const float* __restrict__ x,
                     const float* __restrict__ W,
                     const float* __restrict__ bias,
                     const int*   __restrict__ kernel2,
                     float*       __restrict__ out)
{
    extern __shared__ char smem[];
    const uint32_t sbase = smem_u32(smem);
    const int tid  = threadIdx.x;
    const int wid  = tid >> 5;
    const int lane = tid & 31;
    const int wm   = wid & 3;          // warp M index (4 x 32 rows)
    const int wn   = wid >> 2;         // warp N index (2 x 32 cols)

    int*   sidx_s = reinterpret_cast<int*>(smem + SM_SIDX);
    float* bias_s = reinterpret_cast<float*>(smem + SM_BIAS);

    if (tid < OUTF) bias_s[tid] = bias[tid];

    // ---- One-time: W split -> B_hi/B_lo smem, layout [o][kc] bf16, row stride 528B ----
    for (int idx = tid; idx < OUTF * (KDIM / 2); idx += NTHREADS) {   // 8192 pairs
        const int o   = idx >> 7;
        const int kc0 = (idx & 127) << 1;
        const int k   = kc0 >> 6;
        const int c0  = kc0 & 63;
        const float* wp = W + k * (CC * OUTF) + c0 * OUTF + o;
        const float w0 = wp[0];
        const float w1 = wp[OUTF];
        const __nv_bfloat16 h0 = __float2bfloat16(w0);
        const __nv_bfloat16 h1 = __float2bfloat16(w1);
        const __nv_bfloat16 l0 = __float2bfloat16(w0 - __bfloat162float(h0));
        const __nv_bfloat16 l1 = __float2bfloat16(w1 - __bfloat162float(h1));
        const int off = o * ASTRB + kc0 * 2;
        *reinterpret_cast<uint32_t*>(smem + SM_BHI + off) = pack_bf2(h0, h1);
        *reinterpret_cast<uint32_t*>(smem + SM_BLO + off) = pack_bf2(l0, l1);
    }

    // ---- Tile-invariant ldmatrix per-lane addresses ----
    const int m  = lane >> 3;          // matrix index 0..3
    const int l7 = lane & 7;           // row-within-8
    // A x4: frags = (rows0-7,k0-7),(rows8-15,k0-7),(rows0-7,k8-15),(rows8-15,k8-15)
    const int a_row_off = ((m & 1) << 3) + l7;
    const int a_col_off = (m >> 1) << 4;             // bytes
    const uint32_t aoff0 = (uint32_t)((wm * 32 + a_row_off) * ASTRB + a_col_off);
    const uint32_t aoff1 = aoff0 + 16 * ASTRB;
    const uint32_t ahi0 = sbase + SM_AHI + aoff0;
    const uint32_t ahi1 = sbase + SM_AHI + aoff1;
    const uint32_t alo0 = sbase + SM_ALO + aoff0;
    const uint32_t alo1 = sbase + SM_ALO + aoff1;
    // B x4: regs = (n0-7,k0-7),(n0-7,k8-15),(n8-15,k0-7),(n8-15,k8-15)
    const int b_row_off = ((m >> 1) << 3) + l7;
    const int b_col_off = (m & 1) << 4;              // bytes
    const uint32_t boff0 = (uint32_t)((wn * 32 + b_row_off) * ASTRB + b_col_off);
    const uint32_t boff1 = boff0 + 16 * ASTRB;
    const uint32_t bhi0 = sbase + SM_BHI + boff0;
    const uint32_t bhi1 = sbase + SM_BHI + boff1;
    const uint32_t blo0 = sbase + SM_BLO + boff0;
    const uint32_t blo1 = sbase + SM_BLO + boff1;

    // ---- Tile loop ----
    for (int tile = blockIdx.x; tile < NTILES; tile += GRID) {
        const int b  = tile >> 5;                // 32 tiles per batch
        const int n0 = (tile & 31) * TM;

        sidx_s[tid]            = kernel2[n0 * K2 + tid];
        sidx_s[tid + NTHREADS] = kernel2[n0 * K2 + NTHREADS + tid];
        __syncthreads();

        // ---- Gather x rows, split fp32 -> bf16 hi/lo, store [site][kc] ----
        {
            const float* xb = x + (size_t)b * NN * CC;
            const int l16  = lane & 15;
            const int rsub = lane >> 4;
            #pragma unroll 4
            for (int r = wid * 2 + rsub; r < TM * K2; r += 16) {
                const int s  = r >> 2;
                const int k  = r & 3;
                const int gi = sidx_s[r];
                const float4 v = *reinterpret_cast<const float4*>(xb + (size_t)gi * CC + l16 * 4);
                const __nv_bfloat16 h0 = __float2bfloat16(v.x);
                const __nv_bfloat16 h1 = __float2bfloat16(v.y);
                const __nv_bfloat16 h2 = __float2bfloat16(v.z);
                const __nv_bfloat16 h3 = __float2bfloat16(v.w);
                const __nv_bfloat16 e0 = __float2bfloat16(v.x - __bfloat162float(h0));
                const __nv_bfloat16 e1 = __float2bfloat16(v.y - __bfloat162float(h1));
                const __nv_bfloat16 e2 = __float2bfloat16(v.z - __bfloat162float(h2));
                const __nv_bfloat16 e3 = __float2bfloat16(v.w - __bfloat162float(h3));
                const int off = s * ASTRB + (k * 64 + l16 * 4) * 2;
                uint2 hv, lv;
                hv.x = pack_bf2(h0, h1);
                hv.y = pack_bf2(h2, h3);
                lv.x = pack_bf2(e0, e1);
                lv.y = pack_bf2(e2, e3);
                *reinterpret_cast<uint2*>(smem + SM_AHI + off) = hv;
                *reinterpret_cast<uint2*>(smem + SM_ALO + off) = lv;
            }
        }
        __syncthreads();

        // ---- 3-term MMA: Ahi*Bhi + Ahi*Blo + Alo*Bhi ----
        float acc[2][4][4];
        #pragma unroll
        for (int i = 0; i < 2; ++i)
            #pragma unroll
            for (int j = 0; j < 4; ++j)
                #pragma unroll
                for (int q = 0; q < 4; ++q)
                    acc[i][j][q] = 0.0f;

        #pragma unroll 4
        for (int ks = 0; ks < 16; ++ks) {
            const uint32_t kb = (uint32_t)ks * 32;   // 16 bf16 = 32 bytes per k-step
            uint32_t AH[2][4], AL[2][4], BH[8], BL[8];
            ldsm_x4(AH[0][0], AH[0][1], AH[0][2], AH[0][3], ahi0 + kb);
            ldsm_x4(AH[1][0], AH[1][1], AH[1][2], AH[1][3], ahi1 + kb);
            ldsm_x4(AL[0][0], AL[0][1], AL[0][2], AL[0][3], alo0 + kb);
            ldsm_x4(AL[1][0], AL[1][1], AL[1][2], AL[1][3], alo1 + kb);
            ldsm_x4(BH[0], BH[1], BH[2], BH[3], bhi0 + kb);
            ldsm_x4(BH[4], BH[5], BH[6], BH[7], bhi1 + kb);
            ldsm_x4(BL[0], BL[1], BL[2], BL[3], blo0 + kb);
            ldsm_x4(BL[4], BL[5], BL[6], BL[7], blo1 + kb);
            #pragma unroll
            for (int mi = 0; mi < 2; ++mi) {
                #pragma unroll
                for (int ni = 0; ni < 4; ++ni) {
                    mma_bf16(acc[mi][ni], AH[mi], BH + 2 * ni);
                    mma_bf16(acc[mi][ni], AH[mi], BL + 2 * ni);
                    mma_bf16(acc[mi][ni], AL[mi], BH + 2 * ni);
                }
            }
        }

        // ---- Epilogue: bias + store ----
        {
            const size_t orow = (size_t)b * NN + n0 + wm * 32 + (lane >> 2);
            #pragma unroll
            for (int mi = 0; mi < 2; ++mi) {
                const size_t r0 = orow + mi * 16;
                #pragma unroll
                for (int ni = 0; ni < 4; ++ni) {
                    const int col = wn * 32 + ni * 8 + (lane & 3) * 2;
                    const float b0 = bias_s[col];
                    const float b1 = bias_s[col + 1];
                    float2 v0, v1;
                    v0.x = acc[mi][ni][0] + b0;  v0.y = acc[mi][ni][1] + b1;
                    v1.x = acc[mi][ni][2] + b0;  v1.y = acc[mi][ni][3] + b1;
                    *reinterpret_cast<float2*>(out + r0 * OUTF + col)       = v0;
                    *reinterpret_cast<float2*>(out + (r0 + 8) * OUTF + col) = v1;
                }
            }
        }
        __syncthreads();   // protect A tiles / sidx before next tile's gather
    }
}

extern "C" void kernel_launch(void* const* d_in, const int* in_sizes, int n_in,
                              void* d_out, int out_size)
{
    const float* x    = (const float*)d_in[0];   // [B, N, C]
    const float* W    = (const float*)d_in[1];   // [K2, C, OUT]
    const float* bias = (const float*)d_in[2];   // [OUT]
    const int*   k2   = (const int*)d_in[3];     // [N, K2]
    float*       out  = (float*)d_out;           // [B, N, OUT]

    cudaFuncSetAttribute(conv_mma_kernel,
                         cudaFuncAttributeMaxDynamicSharedMemorySize, SM_TOTAL);
    conv_mma_kernel<<<GRID, NTHREADS, SM_TOTAL>>>(x, W, bias, k2, out);
}

// round 8
// speedup vs baseline: 3.0530x; 1.4233x over previous
#include <cuda_runtime.h>
#include <cuda_bf16.h>
#include <cstdint>
#include <cstddef>

// Problem constants
#define BB   64
#define NN   4096
#define CC   64
#define OUTF 64
#define K2   4
#define TM   128                       // sites per tile (GEMM M)
#define KDIM 256                       // GEMM K = K2*CC
#define NTILES 2048                    // BB * NN / TM
#define GRID 148
#define NTHREADS 512

#define ASTRB 528                      // row stride bytes (264 bf16; odd 16B phase -> ldmatrix conflict-free)

// smem layout (bytes)
#define SM_BIAS 0                      // 64 floats
#define SM_SIDX 256                    // 512 ints
#define SM_AHI  2560                   // 128 rows * 528B = 67584
#define SM_ALO  (SM_AHI + TM * ASTRB)
#define SM_BHI  (SM_ALO + TM * ASTRB)  // 64 rows * 528B = 33792
#define SM_BLO  (SM_BHI + OUTF * ASTRB)
#define SM_TOTAL (SM_BLO + OUTF * ASTRB)   // 205312 bytes

__device__ __forceinline__ uint32_t smem_u32(const void* p) {
    uint32_t a;
    asm("{ .reg .u64 t; cvta.to.shared.u64 t, %1; cvt.u32.u64 %0, t; }" : "=r"(a) : "l"(p));
    return a;
}
__device__ __forceinline__ void ldsm_x4(uint32_t& r0, uint32_t& r1, uint32_t& r2, uint32_t& r3,
                                        uint32_t addr) {
    asm volatile("ldmatrix.sync.aligned.m8n8.x4.shared.b16 {%0,%1,%2,%3}, [%4];"
                 : "=r"(r0), "=r"(r1), "=r"(r2), "=r"(r3) : "r"(addr));
}
__device__ __forceinline__ void mma_bf16(float* acc, const uint32_t* a, const uint32_t* b) {
    asm volatile(
        "mma.sync.aligned.m16n8k16.row.col.f32.bf16.bf16.f32 "
        "{%0,%1,%2,%3}, {%4,%5,%6,%7}, {%8,%9}, {%0,%1,%2,%3};"
        : "+f"(acc[0]), "+f"(acc[1]), "+f"(acc[2]), "+f"(acc[3])
        : "r"(a[0]), "r"(a[1]), "r"(a[2]), "r"(a[3]), "r"(b[0]), "r"(b[1]));
}
__device__ __forceinline__ uint32_t pack_bf2(__nv_bfloat16 a, __nv_bfloat16 b) {
    __nv_bfloat162 t = __halves2bfloat162(a, b);
    uint32_t u;
    memcpy(&u, &t, 4);
    return u;
}

__global__ __launch_bounds__(NTHREADS, 1)
void conv_mma_kernel(const float* __restrict__ x,
                     const float* __restrict__ W,
                     const float* __restrict__ bias,
                     const int*   __restrict__ kernel2,
                     float*       __restrict__ out)
{
    extern __shared__ char smem[];
    const uint32_t sbase = smem_u32(smem);
    const int tid  = threadIdx.x;
    const int wid  = tid >> 5;
    const int lane = tid & 31;
    const int wm   = wid & 3;          // warp M index: 4 groups of 32 rows
    const int wn   = wid >> 2;         // warp N index: 4 groups of 16 cols

    int*   sidx_s = reinterpret_cast<int*>(smem + SM_SIDX);
    float* bias_s = reinterpret_cast<float*>(smem + SM_BIAS);

    if (tid < OUTF) bias_s[tid] = bias[tid];

    // ---- One-time: W split -> B_hi/B_lo smem, layout [o][kc] bf16, row stride 528B ----
    for (int idx = tid; idx < OUTF * (KDIM / 2); idx += NTHREADS) {   // 8192 pairs
        const int o   = idx >> 7;
        const int kc0 = (idx & 127) << 1;
        const int k   = kc0 >> 6;
        const int c0  = kc0 & 63;
        const float* wp = W + k * (CC * OUTF) + c0 * OUTF + o;
        const float w0 = wp[0];
        const float w1 = wp[OUTF];
        const __nv_bfloat16 h0 = __float2bfloat16(w0);
        const __nv_bfloat16 h1 = __float2bfloat16(w1);
        const __nv_bfloat16 l0 = __float2bfloat16(w0 - __bfloat162float(h0));
        const __nv_bfloat16 l1 = __float2bfloat16(w1 - __bfloat162float(h1));
        const int off = o * ASTRB + kc0 * 2;
        *reinterpret_cast<uint32_t*>(smem + SM_BHI + off) = pack_bf2(h0, h1);
        *reinterpret_cast<uint32_t*>(smem + SM_BLO + off) = pack_bf2(l0, l1);
    }

    // ---- Tile-invariant ldmatrix per-lane addresses ----
    const int m  = lane >> 3;          // matrix index 0..3
    const int l7 = lane & 7;           // row-within-8
    // A x4 frags: (rows0-7,k0-7),(rows8-15,k0-7),(rows0-7,k8-15),(rows8-15,k8-15)
    const int a_row_off = ((m & 1) << 3) + l7;
    const int a_col_off = (m >> 1) << 4;             // bytes
    const uint32_t aoff0 = (uint32_t)((wm * 32 + a_row_off) * ASTRB + a_col_off);
    const uint32_t aoff1 = aoff0 + 16 * ASTRB;
    const uint32_t ahi0 = sbase + SM_AHI + aoff0;
    const uint32_t ahi1 = sbase + SM_AHI + aoff1;
    const uint32_t alo0 = sbase + SM_ALO + aoff0;
    const uint32_t alo1 = sbase + SM_ALO + aoff1;
    // B x4 frags: (n0-7,k0-7),(n0-7,k8-15),(n8-15,k0-7),(n8-15,k8-15)
    const int b_row_off = ((m >> 1) << 3) + l7;
    const int b_col_off = (m & 1) << 4;              // bytes
    const uint32_t boff = (uint32_t)((wn * 16 + b_row_off) * ASTRB + b_col_off);
    const uint32_t bhi = sbase + SM_BHI + boff;
    const uint32_t blo = sbase + SM_BLO + boff;

    // ---- Tile loop ----
    for (int tile = blockIdx.x; tile < NTILES; tile += GRID) {
        const int b  = tile >> 5;                // 32 tiles per batch
        const int n0 = (tile & 31) * TM;

        // 512 gather indices, one per thread. Threads reach here only after their
        // own MMA-loop (program order), and sync below covers cross-warp A reuse.
        sidx_s[tid] = kernel2[n0 * K2 + tid];
        __syncthreads();

        // ---- Gather x rows, split fp32 -> bf16 hi/lo, store [site][kc] ----
        {
            const float* xb = x + (size_t)b * NN * CC;
            const int l16  = lane & 15;
            const int rsub = lane >> 4;
            #pragma unroll 8
            for (int r = wid * 2 + rsub; r < TM * K2; r += 32) {
                const int s  = r >> 2;
                const int k  = r & 3;
                const int gi = sidx_s[r];
                const float4 v = *reinterpret_cast<const float4*>(xb + (size_t)gi * CC + l16 * 4);
                const __nv_bfloat16 h0 = __float2bfloat16(v.x);
                const __nv_bfloat16 h1 = __float2bfloat16(v.y);
                const __nv_bfloat16 h2 = __float2bfloat16(v.z);
                const __nv_bfloat16 h3 = __float2bfloat16(v.w);
                const __nv_bfloat16 e0 = __float2bfloat16(v.x - __bfloat162float(h0));
                const __nv_bfloat16 e1 = __float2bfloat16(v.y - __bfloat162float(h1));
                const __nv_bfloat16 e2 = __float2bfloat16(v.z - __bfloat162float(h2));
                const __nv_bfloat16 e3 = __float2bfloat16(v.w - __bfloat162float(h3));
                const int off = s * ASTRB + (k * 64 + l16 * 4) * 2;
                uint2 hv, lv;
                hv.x = pack_bf2(h0, h1);
                hv.y = pack_bf2(h2, h3);
                lv.x = pack_bf2(e0, e1);
                lv.y = pack_bf2(e2, e3);
                *reinterpret_cast<uint2*>(smem + SM_AHI + off) = hv;
                *reinterpret_cast<uint2*>(smem + SM_ALO + off) = lv;
            }
        }
        __syncthreads();

        // ---- 3-term MMA: Ahi*Bhi + Ahi*Blo + Alo*Bhi ----
        float acc[2][2][4];
        #pragma unroll
        for (int i = 0; i < 2; ++i)
            #pragma unroll
            for (int j = 0; j < 2; ++j)
                #pragma unroll
                for (int q = 0; q < 4; ++q)
                    acc[i][j][q] = 0.0f;

        #pragma unroll 4
        for (int ks = 0; ks < 16; ++ks) {
            const uint32_t kb = (uint32_t)ks * 32;   // 16 bf16 = 32 bytes per k-step
            uint32_t AH[2][4], AL[2][4], BH[4], BL[4];
            ldsm_x4(AH[0][0], AH[0][1], AH[0][2], AH[0][3], ahi0 + kb);
            ldsm_x4(AH[1][0], AH[1][1], AH[1][2], AH[1][3], ahi1 + kb);
            ldsm_x4(AL[0][0], AL[0][1], AL[0][2], AL[0][3], alo0 + kb);
            ldsm_x4(AL[1][0], AL[1][1], AL[1][2], AL[1][3], alo1 + kb);
            ldsm_x4(BH[0], BH[1], BH[2], BH[3], bhi + kb);
            ldsm_x4(BL[0], BL[1], BL[2], BL[3], blo + kb);
            #pragma unroll
            for (int mi = 0; mi < 2; ++mi) {
                #pragma unroll
                for (int ni = 0; ni < 2; ++ni) {
                    mma_bf16(acc[mi][ni], AH[mi], BH + 2 * ni);
                    mma_bf16(acc[mi][ni], AH[mi], BL + 2 * ni);
                    mma_bf16(acc[mi][ni], AL[mi], BH + 2 * ni);
                }
            }
        }

        // ---- Epilogue: bias + store ----
        {
            const size_t orow = (size_t)b * NN + n0 + wm * 32 + (lane >> 2);
            #pragma unroll
            for (int mi = 0; mi < 2; ++mi) {
                const size_t r0 = orow + mi * 16;
                #pragma unroll
                for (int ni = 0; ni < 2; ++ni) {
                    const int col = wn * 16 + ni * 8 + (lane & 3) * 2;
                    const float b0 = bias_s[col];
                    const float b1 = bias_s[col + 1];
                    float2 v0, v1;
                    v0.x = acc[mi][ni][0] + b0;  v0.y = acc[mi][ni][1] + b1;
                    v1.x = acc[mi][ni][2] + b0;  v1.y = acc[mi][ni][3] + b1;
                    *reinterpret_cast<float2*>(out + r0 * OUTF + col)       = v0;
                    *reinterpret_cast<float2*>(out + (r0 + 8) * OUTF + col) = v1;
                }
            }
        }
        // No trailing sync needed: next-iteration smem writes (sidx) are ordered
        // behind each thread's own MMA reads, and the loop-top __syncthreads
        // orders them against all other warps' MMA reads of A.
    }
}

extern "C" void kernel_launch(void* const* d_in, const int* in_sizes, int n_in,
                              void* d_out, int out_size)
{
    const float* x    = (const float*)d_in[0];   // [B, N, C]
    const float* W    = (const float*)d_in[1];   // [K2, C, OUT]
    const float* bias = (const float*)d_in[2];   // [OUT]
    const int*   k2   = (const int*)d_in[3];     // [N, K2]
    float*       out  = (float*)d_out;           // [B, N, OUT]

    cudaFuncSetAttribute(conv_mma_kernel,
                         cudaFuncAttributeMaxDynamicSharedMemorySize, SM_TOTAL);
    conv_mma_kernel<<<GRID, NTHREADS, SM_TOTAL>>>(x, W, bias, k2, out);
}